// round 16
// baseline (speedup 1.0000x reference)
#include <cuda_runtime.h>
#include <cuda_bf16.h>
#include <cuda_fp16.h>
#include <cstdint>

#define NN    50000
#define MPAD  50048              // 391 * 128
#define KCH   256
#define HEADS 8
#define OUTC  32
#define NE    800000

#define K1_TILES 782             // 2 x 391
#define HIST_BLOCKS 3125         // 800000 / 256
#define SCAT_BLOCKS 782          // ceil(800000 / 1024)

// dynamic smem layout for f1 (bytes):
//   [0      , 20480) sW buf0  ([arr][128][20] u32, arr stride 10240)
//   [20480  , 40960) sW buf1
//   [40960  , 61440) sA buf0
//   [61440  , 81920) sA buf1
//   [81920  , 82944) s_attn (2 x 128 floats)
#define SM_WBUF   20480
#define SM_ARR    10240
#define SM_AOFF   40960
#define SM_ATTN   81920
#define SM_TOTAL  82944

// ---------------- scratch (static __device__, no allocation) ----------------
__device__ __half   g_xph[(size_t)NN * KCH];    // projected features, fp16
__device__ float    g_al[NN * HEADS];
__device__ float    g_ar[NN * HEADS];
__device__ int      g_deg[NN];
__device__ int      g_rowptr[NN + 1];
__device__ int      g_cursor[NN];
__device__ int      g_csrsrc[NE];
__device__ uint32_t g_whi[KCH * (KCH / 2)];     // W hi, packed bf16x2 [n][k/2]
__device__ uint32_t g_wlo[KCH * (KCH / 2)];     // W lo (residual)

// ---------------- helpers ----------------
__device__ __forceinline__ uint32_t pack_bf2(float a, float b) {
    __nv_bfloat162 t = __halves2bfloat162(__float2bfloat16(a), __float2bfloat16(b));
    return *reinterpret_cast<uint32_t*>(&t);
}
__device__ __forceinline__ uint32_t pack_h2(float a, float b) {
    __half2 t = __floats2half2_rn(a, b);
    return *reinterpret_cast<uint32_t*>(&t);
}
__device__ __forceinline__ void mma_bf16(float* c, const uint32_t* a,
                                         uint32_t b0, uint32_t b1) {
    asm volatile(
        "mma.sync.aligned.m16n8k16.row.col.f32.bf16.bf16.f32 "
        "{%0,%1,%2,%3}, {%4,%5,%6,%7}, {%8,%9}, {%0,%1,%2,%3};"
        : "+f"(c[0]), "+f"(c[1]), "+f"(c[2]), "+f"(c[3])
        : "r"(a[0]), "r"(a[1]), "r"(a[2]), "r"(a[3]), "r"(b0), "r"(b1));
}
__device__ __forceinline__ int ld_idx(const void* ei, int pos, int is64) {
    if (is64) return (int)((const long long*)ei)[pos];
    return ((const int*)ei)[pos];
}
__device__ __forceinline__ void fma8(float* acc, float w, uint4 u) {
    float2 f0 = __half22float2(*(__half2*)&u.x);
    float2 f1 = __half22float2(*(__half2*)&u.y);
    float2 f2 = __half22float2(*(__half2*)&u.z);
    float2 f3 = __half22float2(*(__half2*)&u.w);
    acc[0] += w * f0.x; acc[1] += w * f0.y;
    acc[2] += w * f1.x; acc[3] += w * f1.y;
    acc[4] += w * f2.x; acc[5] += w * f2.y;
    acc[6] += w * f3.x; acc[7] += w * f3.y;
}
__device__ __forceinline__ float expleaky(float lg) {
    float a = lg > 0.f ? lg : 0.2f * lg;
    return __expf(a);
}

// ---------------- kzW: W split (main stream, gates f1) --------------------
__global__ void kzW(const float* __restrict__ W) {
    int i = blockIdx.x * 256 + threadIdx.x;          // n*128 + kk
    int n = i >> 7, kk = i & 127;
    float2 v = *(const float2*)(W + (size_t)n * KCH + kk * 2);
    float hx = __bfloat162float(__float2bfloat16(v.x));
    float hy = __bfloat162float(__float2bfloat16(v.y));
    g_whi[i] = pack_bf2(v.x, v.y);
    g_wlo[i] = pack_bf2(v.x - hx, v.y - hy);
}

// ---------------- kzD: zero degree counters (side stream) -----------------
__global__ void kzD() {
    int i = blockIdx.x * 256 + threadIdx.x;
    if (i < NN) g_deg[i] = 0;
}

// ---------------- kh: dst-degree histogram (side stream) -------------------
__global__ void kh_hist(const void* __restrict__ ei) {
    __shared__ int s_is64;
    int tid = threadIdx.x;
    if (tid == 0) s_is64 = 1;
    __syncthreads();
    if (tid < 64) {
        long long v = ((const long long*)ei)[tid];
        if (v < 0 || v >= NN) s_is64 = 0;   // benign race: all writes = 0
    }
    __syncthreads();
    int is64 = s_is64;
    int e = blockIdx.x * 256 + tid;
    if (e < NE) atomicAdd(&g_deg[ld_idx(ei, NE + e, is64)], 1);
}

// ---------------- F1: GEMM xp = x @ W^T, double-buffered pipeline ----------
// CTA 128x128, warp 32Mx64N, split-bf16 3-product. Two smem buffers: stage
// chunk ch+1 while computing ch -> ONE __syncthreads per chunk, staging
// latency hidden behind MMAs. Scalar fragment LDS (R13-proven, stride-20
// conflict-free).
__global__ __launch_bounds__(256, 2) void f1(const float* __restrict__ x,
                                             const float* __restrict__ attn_l,
                                             const float* __restrict__ attn_r) {
    extern __shared__ char sm[];
    float* s_attn = (float*)(sm + SM_ATTN);

    int tid = threadIdx.x;
    int lane = tid & 31, wid = tid >> 5;
    int bx = blockIdx.x & 1, by = blockIdx.x >> 1;
    int m0 = by * 128;
    int n0 = bx * 128;
    int qr = lane >> 2;        // groupID
    int qc = lane & 3;         // thread-in-group
    int wm = wid & 3;          // M stripe (32 rows)
    int wn = wid >> 2;         // N stripe (64 cols)

    if (tid < 128) s_attn[tid] = attn_l[n0 + tid];
    else           s_attn[128 + tid - 128 + 128 - 128] = 0.f; // placeholder (overwritten below)
    if (tid >= 128) s_attn[128 + (tid - 128)] = attn_r[n0 + tid - 128];

    float acc[2][8][4];        // [m-tile][n-tile][frag]
#pragma unroll
    for (int mt = 0; mt < 2; mt++)
#pragma unroll
        for (int nt = 0; nt < 8; nt++)
#pragma unroll
            for (int j = 0; j < 4; j++) acc[mt][nt][j] = 0.f;

    int rl0 = wm * 32 + qr;
    int nb  = wn * 64;

    // staging coordinates for this thread (4 items/chunk)
    int st_row = tid >> 3;               // rows tid>>3, +32, +64, +96
    int st_f4  = tid & 7;

    // W cp.async per-thread coords (4 iterations of i = tid + 256*j)
    // i in [0,1024): arr = i>>9, row = (i>>2)&127, c4 = i&3

    // ---- prologue: load A ch0, stage chunk 0 into buf0, prefetch A ch1 ----
    float4 pre[4];
#pragma unroll
    for (int j = 0; j < 4; j++) {
        int grow = m0 + st_row + j * 32;
        pre[j] = (grow < NN)
                 ? *(const float4*)(x + (size_t)grow * KCH + st_f4 * 4)
                 : make_float4(0.f, 0.f, 0.f, 0.f);
    }
#pragma unroll
    for (int i = tid; i < 1024; i += 256) {
        int arr = i >> 9;
        int row = (i >> 2) & 127;
        int c4  = i & 3;
        const uint32_t* src = (arr ? g_wlo : g_whi)
                              + (size_t)(n0 + row) * 128 + c4 * 4;
        uint32_t daddr = (uint32_t)__cvta_generic_to_shared(
            sm + arr * SM_ARR + (row * 20 + c4 * 4) * 4);
        asm volatile("cp.async.ca.shared.global [%0], [%1], 16;"
                     :: "r"(daddr), "l"(src));
    }
    asm volatile("cp.async.commit_group;");
#pragma unroll
    for (int j = 0; j < 4; j++) {
        int row = st_row + j * 32;
        float4 v = pre[j];
        float hx = __bfloat162float(__float2bfloat16(v.x));
        float hy = __bfloat162float(__float2bfloat16(v.y));
        float hz = __bfloat162float(__float2bfloat16(v.z));
        float hw = __bfloat162float(__float2bfloat16(v.w));
        *(uint2*)(sm + SM_AOFF + (row * 20 + st_f4 * 2) * 4) =
            make_uint2(pack_bf2(v.x, v.y), pack_bf2(v.z, v.w));
        *(uint2*)(sm + SM_AOFF + SM_ARR + (row * 20 + st_f4 * 2) * 4) =
            make_uint2(pack_bf2(v.x - hx, v.y - hy), pack_bf2(v.z - hz, v.w - hw));
    }
#pragma unroll
    for (int j = 0; j < 4; j++) {
        int grow = m0 + st_row + j * 32;
        pre[j] = (grow < NN)
                 ? *(const float4*)(x + (size_t)grow * KCH + 32 + st_f4 * 4)
                 : make_float4(0.f, 0.f, 0.f, 0.f);
    }
    asm volatile("cp.async.wait_group 0;" ::: "memory");
    __syncthreads();

    for (int ch = 0; ch < 8; ch++) {      // K chunks of 32 (16 u32)
        int cur = ch & 1;
        int nxt = cur ^ 1;
        char* smW = sm + cur * SM_WBUF;
        char* smA = sm + SM_AOFF + cur * SM_WBUF;

        // ---- stage chunk ch+1 into the idle buffer ----
        if (ch < 7) {
#pragma unroll
            for (int i = tid; i < 1024; i += 256) {
                int arr = i >> 9;
                int row = (i >> 2) & 127;
                int c4  = i & 3;
                const uint32_t* src = (arr ? g_wlo : g_whi)
                                      + (size_t)(n0 + row) * 128 + (ch + 1) * 16 + c4 * 4;
                uint32_t daddr = (uint32_t)__cvta_generic_to_shared(
                    sm + nxt * SM_WBUF + arr * SM_ARR + (row * 20 + c4 * 4) * 4);
                asm volatile("cp.async.ca.shared.global [%0], [%1], 16;"
                             :: "r"(daddr), "l"(src));
            }
            asm volatile("cp.async.commit_group;");
#pragma unroll
            for (int j = 0; j < 4; j++) {
                int row = st_row + j * 32;
                float4 v = pre[j];
                float hx = __bfloat162float(__float2bfloat16(v.x));
                float hy = __bfloat162float(__float2bfloat16(v.y));
                float hz = __bfloat162float(__float2bfloat16(v.z));
                float hw = __bfloat162float(__float2bfloat16(v.w));
                char* dA = sm + SM_AOFF + nxt * SM_WBUF;
                *(uint2*)(dA + (row * 20 + st_f4 * 2) * 4) =
                    make_uint2(pack_bf2(v.x, v.y), pack_bf2(v.z, v.w));
                *(uint2*)(dA + SM_ARR + (row * 20 + st_f4 * 2) * 4) =
                    make_uint2(pack_bf2(v.x - hx, v.y - hy),
                               pack_bf2(v.z - hz, v.w - hw));
            }
            if (ch < 6) {
#pragma unroll
                for (int j = 0; j < 4; j++) {
                    int grow = m0 + st_row + j * 32;
                    pre[j] = (grow < NN)
                             ? *(const float4*)(x + (size_t)grow * KCH + (ch + 2) * 32 + st_f4 * 4)
                             : make_float4(0.f, 0.f, 0.f, 0.f);
                }
            }
        }

        // ---- compute chunk ch from the current buffer ----
        const uint32_t* A0 = (const uint32_t*)(smA);
        const uint32_t* A1 = (const uint32_t*)(smA + SM_ARR);
        const uint32_t* W0 = (const uint32_t*)(smW);
        const uint32_t* W1 = (const uint32_t*)(smW + SM_ARR);
#pragma unroll
        for (int kc = 0; kc < 2; kc++) {          // 2 x k16 per chunk
            int kl = kc * 8;
            uint32_t ahi[2][4], alo[2][4];
#pragma unroll
            for (int mt = 0; mt < 2; mt++) {
                int ra = (rl0 + mt * 16) * 20, rb = ra + 8 * 20;
                ahi[mt][0] = A0[ra + kl + qc];     ahi[mt][1] = A0[rb + kl + qc];
                ahi[mt][2] = A0[ra + kl + qc + 4]; ahi[mt][3] = A0[rb + kl + qc + 4];
                alo[mt][0] = A1[ra + kl + qc];     alo[mt][1] = A1[rb + kl + qc];
                alo[mt][2] = A1[ra + kl + qc + 4]; alo[mt][3] = A1[rb + kl + qc + 4];
            }
#pragma unroll
            for (int nt = 0; nt < 8; nt++) {
                int nr = (nb + nt * 8 + qr) * 20;
                uint32_t bh0 = W0[nr + kl + qc];
                uint32_t bh1 = W0[nr + kl + qc + 4];
                uint32_t bl0 = W1[nr + kl + qc];
                uint32_t bl1 = W1[nr + kl + qc + 4];
#pragma unroll
                for (int mt = 0; mt < 2; mt++) {
                    mma_bf16(acc[mt][nt], ahi[mt], bh0, bh1);
                    mma_bf16(acc[mt][nt], ahi[mt], bl0, bl1);
                    mma_bf16(acc[mt][nt], alo[mt], bh0, bh1);
                }
            }
        }

        if (ch < 7) {
            asm volatile("cp.async.wait_group 0;" ::: "memory");
            __syncthreads();
        }
    }

    // ---- epilogue: write xp as fp16 ----
#pragma unroll
    for (int mt = 0; mt < 2; mt++) {
        int row0 = m0 + rl0 + mt * 16;
        int row1 = row0 + 8;
        bool v0 = row0 < NN, v1 = row1 < NN;
#pragma unroll
        for (int nt = 0; nt < 8; nt++) {
            int col = n0 + nb + nt * 8 + qc * 2;
            if (v0) *(uint32_t*)(g_xph + (size_t)row0 * KCH + col) =
                        pack_h2(acc[mt][nt][0], acc[mt][nt][1]);
            if (v1) *(uint32_t*)(g_xph + (size_t)row1 * KCH + col) =
                        pack_h2(acc[mt][nt][2], acc[mt][nt][3]);
        }
    }

    // ---- fused al/ar (fp32, from registers) ----
#pragma unroll
    for (int hl = 0; hl < 2; hl++) {
#pragma unroll
        for (int mt = 0; mt < 2; mt++) {
            float sl0 = 0.f, sr0 = 0.f, sl1 = 0.f, sr1 = 0.f;
#pragma unroll
            for (int t = 0; t < 4; t++) {
                int nt = hl * 4 + t;
                int c = nb + nt * 8 + qc * 2;
                float L0 = s_attn[c], L1 = s_attn[c + 1];
                float R0 = s_attn[128 + c], R1 = s_attn[128 + c + 1];
                sl0 += acc[mt][nt][0] * L0 + acc[mt][nt][1] * L1;
                sr0 += acc[mt][nt][0] * R0 + acc[mt][nt][1] * R1;
                sl1 += acc[mt][nt][2] * L0 + acc[mt][nt][3] * L1;
                sr1 += acc[mt][nt][2] * R0 + acc[mt][nt][3] * R1;
            }
            sl0 += __shfl_xor_sync(0xffffffffu, sl0, 1);
            sl0 += __shfl_xor_sync(0xffffffffu, sl0, 2);
            sr0 += __shfl_xor_sync(0xffffffffu, sr0, 1);
            sr0 += __shfl_xor_sync(0xffffffffu, sr0, 2);
            sl1 += __shfl_xor_sync(0xffffffffu, sl1, 1);
            sl1 += __shfl_xor_sync(0xffffffffu, sl1, 2);
            sr1 += __shfl_xor_sync(0xffffffffu, sr1, 1);
            sr1 += __shfl_xor_sync(0xffffffffu, sr1, 2);
            if (qc == 0) {
                int head = bx * 4 + wn * 2 + hl;
                int row0 = m0 + rl0 + mt * 16;
                int row1 = row0 + 8;
                if (row0 < NN) { g_al[row0 * HEADS + head] = sl0;
                                 g_ar[row0 * HEADS + head] = sr0; }
                if (row1 < NN) { g_al[row1 * HEADS + head] = sl1;
                                 g_ar[row1 * HEADS + head] = sr1; }
            }
        }
    }
}

// ---------------- k4: single-block exclusive scan -> rowptr/cursor -------
__global__ void k4_scan() {
    __shared__ int swarp[32];
    __shared__ int stot;
    int tid = threadIdx.x, lane = tid & 31, wid = tid >> 5;
    int carry = 0;
    for (int base = 0; base < NN; base += 1024) {
        int i = base + tid;
        int v = (i < NN) ? g_deg[i] : 0;
        int incl = v;
#pragma unroll
        for (int d = 1; d < 32; d <<= 1) {
            int t = __shfl_up_sync(0xffffffffu, incl, d);
            if (lane >= d) incl += t;
        }
        if (lane == 31) swarp[wid] = incl;
        __syncthreads();
        if (wid == 0) {
            int wv = swarp[lane];
            int wi = wv;
#pragma unroll
            for (int d = 1; d < 32; d <<= 1) {
                int t = __shfl_up_sync(0xffffffffu, wi, d);
                if (lane >= d) wi += t;
            }
            if (lane == 31) stot = wi;
            swarp[lane] = wi - wv;
        }
        __syncthreads();
        int excl = carry + swarp[wid] + incl - v;
        if (i < NN) { g_rowptr[i] = excl; g_cursor[i] = excl; }
        carry += stot;
        __syncthreads();
    }
    if (tid == 0) g_rowptr[NN] = carry;
}

// ---------------- k5: scatter edges into CSR buckets ----------------
__global__ void k5_scatter(const void* __restrict__ ei) {
    __shared__ int s_is64;
    int tid = threadIdx.x;
    if (tid == 0) s_is64 = 1;
    __syncthreads();
    if (tid < 64) {
        long long v = ((const long long*)ei)[tid];
        if (v < 0 || v >= NN) s_is64 = 0;
    }
    __syncthreads();
    int is64 = s_is64;
    int base = blockIdx.x * 1024 + tid;

    int s[4], d[4];
    bool val[4];
#pragma unroll
    for (int j = 0; j < 4; j++) {
        int e = base + j * 256;
        val[j] = e < NE;
        if (val[j]) {
            s[j] = ld_idx(ei, e, is64);
            d[j] = ld_idx(ei, NE + e, is64);
        }
    }
#pragma unroll
    for (int j = 0; j < 4; j++) {
        if (val[j]) {
            int pos = atomicAdd(&g_cursor[d[j]], 1);
            g_csrsrc[pos] = s[j];
        }
    }
}

// ---------------- k6: fused softmax + aggregate, 4 chains ----------------
__global__ __launch_bounds__(256) void k6_gather(float* __restrict__ out) {
    int node = blockIdx.x * 8 + (threadIdx.x >> 5);
    if (node >= NN) return;
    int lane = threadIdx.x & 31;
    int c0 = lane * 8;
    int h  = lane >> 2;

    float arn = g_ar[node * HEADS + h];

    float ca[8] = {0,0,0,0,0,0,0,0};
    float cb[8] = {0,0,0,0,0,0,0,0};
    float cc[8] = {0,0,0,0,0,0,0,0};
    float cd[8] = {0,0,0,0,0,0,0,0};
    float wa, wb = 0.f, wc = 0.f, wd = 0.f;

    // seed chain a with the self loop
    {
        float w = expleaky(g_al[node * HEADS + h] + arn);
        wa = w;
        uint4 u = *(const uint4*)(g_xph + (size_t)node * KCH + c0);
        fma8(ca, w, u);
    }

    int p   = g_rowptr[node];
    int end = g_rowptr[node + 1];

    for (; p + 4 <= end; p += 4) {
        int s0 = g_csrsrc[p];
        int s1 = g_csrsrc[p + 1];
        int s2 = g_csrsrc[p + 2];
        int s3 = g_csrsrc[p + 3];
        float l0 = g_al[s0 * HEADS + h];
        float l1 = g_al[s1 * HEADS + h];
        float l2 = g_al[s2 * HEADS + h];
        float l3 = g_al[s3 * HEADS + h];
        uint4 u0 = *(const uint4*)(g_xph + (size_t)s0 * KCH + c0);
        uint4 u1 = *(const uint4*)(g_xph + (size_t)s1 * KCH + c0);
        uint4 u2 = *(const uint4*)(g_xph + (size_t)s2 * KCH + c0);
        uint4 u3 = *(const uint4*)(g_xph + (size_t)s3 * KCH + c0);
        float w0 = expleaky(l0 + arn);
        float w1 = expleaky(l1 + arn);
        float w2 = expleaky(l2 + arn);
        float w3 = expleaky(l3 + arn);
        wa += w0; wb += w1; wc += w2; wd += w3;
        fma8(ca, w0, u0);
        fma8(cb, w1, u1);
        fma8(cc, w2, u2);
        fma8(cd, w3, u3);
    }
    for (; p < end; p++) {
        int s0 = g_csrsrc[p];
        float w = expleaky(g_al[s0 * HEADS + h] + arn);
        wa += w;
        uint4 u = *(const uint4*)(g_xph + (size_t)s0 * KCH + c0);
        fma8(ca, w, u);
    }

    float inv = 1.f / fmaxf(wa + wb + wc + wd, 1e-6f);
    float* op = out + (size_t)node * KCH + c0;
    *(float4*)(op)     = make_float4((ca[0]+cb[0]+cc[0]+cd[0]) * inv,
                                     (ca[1]+cb[1]+cc[1]+cd[1]) * inv,
                                     (ca[2]+cb[2]+cc[2]+cd[2]) * inv,
                                     (ca[3]+cb[3]+cc[3]+cd[3]) * inv);
    *(float4*)(op + 4) = make_float4((ca[4]+cb[4]+cc[4]+cd[4]) * inv,
                                     (ca[5]+cb[5]+cc[5]+cd[5]) * inv,
                                     (ca[6]+cb[6]+cc[6]+cd[6]) * inv,
                                     (ca[7]+cb[7]+cc[7]+cd[7]) * inv);
}

// ---------------- launch: fork CSR chain onto a side stream ---------------
extern "C" void kernel_launch(void* const* d_in, const int* in_sizes, int n_in,
                              void* d_out, int out_size) {
    const float* x      = (const float*)d_in[0];
    const void*  ei     = d_in[1];
    const float* W      = (const float*)d_in[2];
    const float* attn_l = (const float*)d_in[3];
    const float* attn_r = (const float*)d_in[4];
    float*       out    = (float*)d_out;

    cudaFuncSetAttribute(f1, cudaFuncAttributeMaxDynamicSharedMemorySize, SM_TOTAL);

    cudaStream_t s2;
    cudaEvent_t evFork, evJoin;
    cudaStreamCreateWithFlags(&s2, cudaStreamNonBlocking);
    cudaEventCreateWithFlags(&evFork, cudaEventDisableTiming);
    cudaEventCreateWithFlags(&evJoin, cudaEventDisableTiming);

    cudaEventRecord(evFork, 0);
    cudaStreamWaitEvent(s2, evFork, 0);

    // side branch: CSR build (independent of the GEMM)
    kzD<<<(NN + 255) / 256, 256, 0, s2>>>();
    kh_hist<<<HIST_BLOCKS, 256, 0, s2>>>(ei);
    k4_scan<<<1, 1024, 0, s2>>>();
    k5_scatter<<<SCAT_BLOCKS, 256, 0, s2>>>(ei);
    cudaEventRecord(evJoin, s2);

    // main branch: W split + GEMM (runs concurrently with CSR build)
    kzW<<<128, 256>>>(W);
    f1<<<K1_TILES, 256, SM_TOTAL>>>(x, attn_l, attn_r);

    cudaStreamWaitEvent(0, evJoin, 0);                 // join before gather
    k6_gather<<<(NN + 7) / 8, 256>>>(out);

    cudaEventDestroy(evFork);
    cudaEventDestroy(evJoin);
    cudaStreamDestroy(s2);
}

// round 17
// speedup vs baseline: 1.1124x; 1.1124x over previous
#include <cuda_runtime.h>
#include <cuda_bf16.h>
#include <cuda_fp16.h>
#include <cstdint>

#define NN    50000
#define MPAD  50048              // 391 * 128
#define KCH   256
#define HEADS 8
#define OUTC  32
#define NE    800000

#define K1_TILES 782             // 2 x 391
#define HIST_BLOCKS 3125         // 800000 / 256
#define SCAT_BLOCKS 782          // ceil(800000 / 1024)

// ---------------- scratch (static __device__, no allocation) ----------------
__device__ __half   g_xph[(size_t)NN * KCH];    // projected features, fp16
__device__ float    g_al[NN * HEADS];
__device__ float    g_ar[NN * HEADS];
__device__ int      g_deg[NN];
__device__ int      g_rowptr[NN + 1];
__device__ int      g_cursor[NN];
__device__ int      g_csrsrc[NE];
__device__ uint32_t g_wh[KCH * (KCH / 2)];      // W as packed fp16x2 [n][k/2]

// ---------------- helpers ----------------
__device__ __forceinline__ uint32_t pack_h2(float a, float b) {
    __half2 t = __floats2half2_rn(a, b);
    return *reinterpret_cast<uint32_t*>(&t);
}
// fp16 MMA m16n8k16, fp32 accumulate
__device__ __forceinline__ void mma_f16(float* c, const uint32_t* a,
                                        uint32_t b0, uint32_t b1) {
    asm volatile(
        "mma.sync.aligned.m16n8k16.row.col.f32.f16.f16.f32 "
        "{%0,%1,%2,%3}, {%4,%5,%6,%7}, {%8,%9}, {%0,%1,%2,%3};"
        : "+f"(c[0]), "+f"(c[1]), "+f"(c[2]), "+f"(c[3])
        : "r"(a[0]), "r"(a[1]), "r"(a[2]), "r"(a[3]), "r"(b0), "r"(b1));
}
__device__ __forceinline__ int ld_idx(const void* ei, int pos, int is64) {
    if (is64) return (int)((const long long*)ei)[pos];
    return ((const int*)ei)[pos];
}
__device__ __forceinline__ void fma8(float* acc, float w, uint4 u) {
    float2 f0 = __half22float2(*(__half2*)&u.x);
    float2 f1 = __half22float2(*(__half2*)&u.y);
    float2 f2 = __half22float2(*(__half2*)&u.z);
    float2 f3 = __half22float2(*(__half2*)&u.w);
    acc[0] += w * f0.x; acc[1] += w * f0.y;
    acc[2] += w * f1.x; acc[3] += w * f1.y;
    acc[4] += w * f2.x; acc[5] += w * f2.y;
    acc[6] += w * f3.x; acc[7] += w * f3.y;
}
__device__ __forceinline__ float expleaky(float lg) {
    float a = lg > 0.f ? lg : 0.2f * lg;
    return __expf(a);
}

// ---------------- kzW: W -> packed fp16 (main stream, gates f1) ------------
__global__ void kzW(const float* __restrict__ W) {
    int i = blockIdx.x * 256 + threadIdx.x;          // n*128 + kk
    int n = i >> 7, kk = i & 127;
    float2 v = *(const float2*)(W + (size_t)n * KCH + kk * 2);
    g_wh[i] = pack_h2(v.x, v.y);
}

// ---------------- kzD: zero degree counters (side stream) -----------------
__global__ void kzD() {
    int i = blockIdx.x * 256 + threadIdx.x;
    if (i < NN) g_deg[i] = 0;
}

// ---------------- kh: dst-degree histogram (side stream) -------------------
__global__ void kh_hist(const void* __restrict__ ei) {
    __shared__ int s_is64;
    int tid = threadIdx.x;
    if (tid == 0) s_is64 = 1;
    __syncthreads();
    if (tid < 64) {
        long long v = ((const long long*)ei)[tid];
        if (v < 0 || v >= NN) s_is64 = 0;   // benign race: all writes = 0
    }
    __syncthreads();
    int is64 = s_is64;
    int e = blockIdx.x * 256 + tid;
    if (e < NE) atomicAdd(&g_deg[ld_idx(ei, NE + e, is64)], 1);
}

// ---------------- F1: GEMM xp = x @ W^T, fp16 2-product split --------------
// CTA 128x128, warp 32Mx64N. A split into fp16 hi+lo (exact to (2^-11)^2);
// W single fp16 (GEMM err ~4.9e-4 rel, budgeted). 2 MMAs per tile step.
// smem rows stride-20 u32 -> conflict-free fragment LDS (R13-proven).
__global__ __launch_bounds__(256, 2) void f1(const float* __restrict__ x,
                                             const float* __restrict__ attn_l,
                                             const float* __restrict__ attn_r) {
    __shared__ uint32_t sW[128][20];      // [n][k-u32], cols 0..15 used
    __shared__ uint32_t sA[2][128][20];   // [hi/lo][m][k-u32]
    __shared__ float    s_attn[2][128];

    int tid = threadIdx.x;
    int lane = tid & 31, wid = tid >> 5;
    int bx = blockIdx.x & 1, by = blockIdx.x >> 1;
    int m0 = by * 128;
    int n0 = bx * 128;
    int qr = lane >> 2;        // groupID
    int qc = lane & 3;         // thread-in-group
    int wm = wid & 3;          // M stripe (32 rows)
    int wn = wid >> 2;         // N stripe (64 cols)

    if (tid < 128) s_attn[0][tid] = attn_l[n0 + tid];
    else           s_attn[1][tid - 128] = attn_r[n0 + tid - 128];

    float acc[2][8][4];        // [m-tile][n-tile][frag]
#pragma unroll
    for (int mt = 0; mt < 2; mt++)
#pragma unroll
        for (int nt = 0; nt < 8; nt++)
#pragma unroll
            for (int j = 0; j < 4; j++) acc[mt][nt][j] = 0.f;

    int rl0 = wm * 32 + qr;
    int nb  = wn * 64;

    // staging coordinates for this thread (4 items/chunk)
    int st_row = tid >> 3;               // rows tid>>3, +32, +64, +96
    int st_f4  = tid & 7;

    // ---- prologue: prefetch A chunk 0 into registers ----
    float4 pre[4];
#pragma unroll
    for (int j = 0; j < 4; j++) {
        int grow = m0 + st_row + j * 32;
        pre[j] = (grow < NN)
                 ? *(const float4*)(x + (size_t)grow * KCH + st_f4 * 4)
                 : make_float4(0.f, 0.f, 0.f, 0.f);
    }

    for (int ch = 0; ch < 8; ch++) {      // K chunks of 32 (16 u32)
        // ---- W chunk via cp.async (512 uint4: 128 rows x 4) ----
#pragma unroll
        for (int i = tid; i < 512; i += 256) {
            int row = i >> 2;
            int c4  = i & 3;
            const uint32_t* src = g_wh + (size_t)(n0 + row) * 128 + ch * 16 + c4 * 4;
            uint32_t daddr = (uint32_t)__cvta_generic_to_shared(&sW[row][c4 * 4]);
            asm volatile("cp.async.ca.shared.global [%0], [%1], 16;"
                         :: "r"(daddr), "l"(src));
        }
        asm volatile("cp.async.commit_group;");

        // ---- convert prefetched A (chunk ch) -> fp16 hi/lo smem ----
#pragma unroll
        for (int j = 0; j < 4; j++) {
            int row = st_row + j * 32;
            float4 v = pre[j];
            float hx = __half2float(__float2half_rn(v.x));
            float hy = __half2float(__float2half_rn(v.y));
            float hz = __half2float(__float2half_rn(v.z));
            float hw = __half2float(__float2half_rn(v.w));
            *(uint2*)&sA[0][row][st_f4 * 2] =
                make_uint2(pack_h2(v.x, v.y), pack_h2(v.z, v.w));
            *(uint2*)&sA[1][row][st_f4 * 2] =
                make_uint2(pack_h2(v.x - hx, v.y - hy), pack_h2(v.z - hz, v.w - hw));
        }

        // ---- prefetch A (chunk ch+1) ----
        if (ch < 7) {
#pragma unroll
            for (int j = 0; j < 4; j++) {
                int grow = m0 + st_row + j * 32;
                pre[j] = (grow < NN)
                         ? *(const float4*)(x + (size_t)grow * KCH + (ch + 1) * 32 + st_f4 * 4)
                         : make_float4(0.f, 0.f, 0.f, 0.f);
            }
        }

        asm volatile("cp.async.wait_group 0;" ::: "memory");
        __syncthreads();

#pragma unroll
        for (int kc = 0; kc < 2; kc++) {          // 2 x k16 per chunk
            int kl = kc * 8;
            uint32_t ahi[2][4], alo[2][4];
#pragma unroll
            for (int mt = 0; mt < 2; mt++) {
                int ra = rl0 + mt * 16, rb = ra + 8;
                ahi[mt][0] = sA[0][ra][kl + qc];     ahi[mt][1] = sA[0][rb][kl + qc];
                ahi[mt][2] = sA[0][ra][kl + qc + 4]; ahi[mt][3] = sA[0][rb][kl + qc + 4];
                alo[mt][0] = sA[1][ra][kl + qc];     alo[mt][1] = sA[1][rb][kl + qc];
                alo[mt][2] = sA[1][ra][kl + qc + 4]; alo[mt][3] = sA[1][rb][kl + qc + 4];
            }
#pragma unroll
            for (int nt = 0; nt < 8; nt++) {
                int nr = nb + nt * 8 + qr;
                uint32_t b0 = sW[nr][kl + qc];
                uint32_t b1 = sW[nr][kl + qc + 4];
#pragma unroll
                for (int mt = 0; mt < 2; mt++) {
                    mma_f16(acc[mt][nt], ahi[mt], b0, b1);
                    mma_f16(acc[mt][nt], alo[mt], b0, b1);
                }
            }
        }
        __syncthreads();
    }

    // ---- epilogue: write xp as fp16 ----
#pragma unroll
    for (int mt = 0; mt < 2; mt++) {
        int row0 = m0 + rl0 + mt * 16;
        int row1 = row0 + 8;
        bool v0 = row0 < NN, v1 = row1 < NN;
#pragma unroll
        for (int nt = 0; nt < 8; nt++) {
            int col = n0 + nb + nt * 8 + qc * 2;
            if (v0) *(uint32_t*)(g_xph + (size_t)row0 * KCH + col) =
                        pack_h2(acc[mt][nt][0], acc[mt][nt][1]);
            if (v1) *(uint32_t*)(g_xph + (size_t)row1 * KCH + col) =
                        pack_h2(acc[mt][nt][2], acc[mt][nt][3]);
        }
    }

    // ---- fused al/ar (fp32, from registers) ----
#pragma unroll
    for (int hl = 0; hl < 2; hl++) {
#pragma unroll
        for (int mt = 0; mt < 2; mt++) {
            float sl0 = 0.f, sr0 = 0.f, sl1 = 0.f, sr1 = 0.f;
#pragma unroll
            for (int t = 0; t < 4; t++) {
                int nt = hl * 4 + t;
                int c = nb + nt * 8 + qc * 2;
                float L0 = s_attn[0][c], L1 = s_attn[0][c + 1];
                float R0 = s_attn[1][c], R1 = s_attn[1][c + 1];
                sl0 += acc[mt][nt][0] * L0 + acc[mt][nt][1] * L1;
                sr0 += acc[mt][nt][0] * R0 + acc[mt][nt][1] * R1;
                sl1 += acc[mt][nt][2] * L0 + acc[mt][nt][3] * L1;
                sr1 += acc[mt][nt][2] * R0 + acc[mt][nt][3] * R1;
            }
            sl0 += __shfl_xor_sync(0xffffffffu, sl0, 1);
            sl0 += __shfl_xor_sync(0xffffffffu, sl0, 2);
            sr0 += __shfl_xor_sync(0xffffffffu, sr0, 1);
            sr0 += __shfl_xor_sync(0xffffffffu, sr0, 2);
            sl1 += __shfl_xor_sync(0xffffffffu, sl1, 1);
            sl1 += __shfl_xor_sync(0xffffffffu, sl1, 2);
            sr1 += __shfl_xor_sync(0xffffffffu, sr1, 1);
            sr1 += __shfl_xor_sync(0xffffffffu, sr1, 2);
            if (qc == 0) {
                int head = bx * 4 + wn * 2 + hl;
                int row0 = m0 + rl0 + mt * 16;
                int row1 = row0 + 8;
                if (row0 < NN) { g_al[row0 * HEADS + head] = sl0;
                                 g_ar[row0 * HEADS + head] = sr0; }
                if (row1 < NN) { g_al[row1 * HEADS + head] = sl1;
                                 g_ar[row1 * HEADS + head] = sr1; }
            }
        }
    }
}

// ---------------- k4: single-block exclusive scan -> rowptr/cursor -------
__global__ void k4_scan() {
    __shared__ int swarp[32];
    __shared__ int stot;
    int tid = threadIdx.x, lane = tid & 31, wid = tid >> 5;
    int carry = 0;
    for (int base = 0; base < NN; base += 1024) {
        int i = base + tid;
        int v = (i < NN) ? g_deg[i] : 0;
        int incl = v;
#pragma unroll
        for (int d = 1; d < 32; d <<= 1) {
            int t = __shfl_up_sync(0xffffffffu, incl, d);
            if (lane >= d) incl += t;
        }
        if (lane == 31) swarp[wid] = incl;
        __syncthreads();
        if (wid == 0) {
            int wv = swarp[lane];
            int wi = wv;
#pragma unroll
            for (int d = 1; d < 32; d <<= 1) {
                int t = __shfl_up_sync(0xffffffffu, wi, d);
                if (lane >= d) wi += t;
            }
            if (lane == 31) stot = wi;
            swarp[lane] = wi - wv;
        }
        __syncthreads();
        int excl = carry + swarp[wid] + incl - v;
        if (i < NN) { g_rowptr[i] = excl; g_cursor[i] = excl; }
        carry += stot;
        __syncthreads();
    }
    if (tid == 0) g_rowptr[NN] = carry;
}

// ---------------- k5: scatter edges into CSR buckets ----------------
__global__ void k5_scatter(const void* __restrict__ ei) {
    __shared__ int s_is64;
    int tid = threadIdx.x;
    if (tid == 0) s_is64 = 1;
    __syncthreads();
    if (tid < 64) {
        long long v = ((const long long*)ei)[tid];
        if (v < 0 || v >= NN) s_is64 = 0;
    }
    __syncthreads();
    int is64 = s_is64;
    int base = blockIdx.x * 1024 + tid;

    int s[4], d[4];
    bool val[4];
#pragma unroll
    for (int j = 0; j < 4; j++) {
        int e = base + j * 256;
        val[j] = e < NE;
        if (val[j]) {
            s[j] = ld_idx(ei, e, is64);
            d[j] = ld_idx(ei, NE + e, is64);
        }
    }
#pragma unroll
    for (int j = 0; j < 4; j++) {
        if (val[j]) {
            int pos = atomicAdd(&g_cursor[d[j]], 1);
            g_csrsrc[pos] = s[j];
        }
    }
}

// ---------------- k6: fused softmax + aggregate, 4 chains ----------------
__global__ __launch_bounds__(256) void k6_gather(float* __restrict__ out) {
    int node = blockIdx.x * 8 + (threadIdx.x >> 5);
    if (node >= NN) return;
    int lane = threadIdx.x & 31;
    int c0 = lane * 8;
    int h  = lane >> 2;

    float arn = g_ar[node * HEADS + h];

    float ca[8] = {0,0,0,0,0,0,0,0};
    float cb[8] = {0,0,0,0,0,0,0,0};
    float cc[8] = {0,0,0,0,0,0,0,0};
    float cd[8] = {0,0,0,0,0,0,0,0};
    float wa, wb = 0.f, wc = 0.f, wd = 0.f;

    // seed chain a with the self loop
    {
        float w = expleaky(g_al[node * HEADS + h] + arn);
        wa = w;
        uint4 u = *(const uint4*)(g_xph + (size_t)node * KCH + c0);
        fma8(ca, w, u);
    }

    int p   = g_rowptr[node];
    int end = g_rowptr[node + 1];

    for (; p + 4 <= end; p += 4) {
        int s0 = g_csrsrc[p];
        int s1 = g_csrsrc[p + 1];
        int s2 = g_csrsrc[p + 2];
        int s3 = g_csrsrc[p + 3];
        float l0 = g_al[s0 * HEADS + h];
        float l1 = g_al[s1 * HEADS + h];
        float l2 = g_al[s2 * HEADS + h];
        float l3 = g_al[s3 * HEADS + h];
        uint4 u0 = *(const uint4*)(g_xph + (size_t)s0 * KCH + c0);
        uint4 u1 = *(const uint4*)(g_xph + (size_t)s1 * KCH + c0);
        uint4 u2 = *(const uint4*)(g_xph + (size_t)s2 * KCH + c0);
        uint4 u3 = *(const uint4*)(g_xph + (size_t)s3 * KCH + c0);
        float w0 = expleaky(l0 + arn);
        float w1 = expleaky(l1 + arn);
        float w2 = expleaky(l2 + arn);
        float w3 = expleaky(l3 + arn);
        wa += w0; wb += w1; wc += w2; wd += w3;
        fma8(ca, w0, u0);
        fma8(cb, w1, u1);
        fma8(cc, w2, u2);
        fma8(cd, w3, u3);
    }
    for (; p < end; p++) {
        int s0 = g_csrsrc[p];
        float w = expleaky(g_al[s0 * HEADS + h] + arn);
        wa += w;
        uint4 u = *(const uint4*)(g_xph + (size_t)s0 * KCH + c0);
        fma8(ca, w, u);
    }

    float inv = 1.f / fmaxf(wa + wb + wc + wd, 1e-6f);
    float* op = out + (size_t)node * KCH + c0;
    *(float4*)(op)     = make_float4((ca[0]+cb[0]+cc[0]+cd[0]) * inv,
                                     (ca[1]+cb[1]+cc[1]+cd[1]) * inv,
                                     (ca[2]+cb[2]+cc[2]+cd[2]) * inv,
                                     (ca[3]+cb[3]+cc[3]+cd[3]) * inv);
    *(float4*)(op + 4) = make_float4((ca[4]+cb[4]+cc[4]+cd[4]) * inv,
                                     (ca[5]+cb[5]+cc[5]+cd[5]) * inv,
                                     (ca[6]+cb[6]+cc[6]+cd[6]) * inv,
                                     (ca[7]+cb[7]+cc[7]+cd[7]) * inv);
}

// ---------------- launch: fork CSR chain onto a side stream ---------------
extern "C" void kernel_launch(void* const* d_in, const int* in_sizes, int n_in,
                              void* d_out, int out_size) {
    const float* x      = (const float*)d_in[0];
    const void*  ei     = d_in[1];
    const float* W      = (const float*)d_in[2];
    const float* attn_l = (const float*)d_in[3];
    const float* attn_r = (const float*)d_in[4];
    float*       out    = (float*)d_out;

    cudaStream_t s2;
    cudaEvent_t evFork, evJoin;
    cudaStreamCreateWithFlags(&s2, cudaStreamNonBlocking);
    cudaEventCreateWithFlags(&evFork, cudaEventDisableTiming);
    cudaEventCreateWithFlags(&evJoin, cudaEventDisableTiming);

    cudaEventRecord(evFork, 0);
    cudaStreamWaitEvent(s2, evFork, 0);

    // side branch: CSR build (independent of the GEMM)
    kzD<<<(NN + 255) / 256, 256, 0, s2>>>();
    kh_hist<<<HIST_BLOCKS, 256, 0, s2>>>(ei);
    k4_scan<<<1, 1024, 0, s2>>>();
    k5_scatter<<<SCAT_BLOCKS, 256, 0, s2>>>(ei);
    cudaEventRecord(evJoin, s2);

    // main branch: W convert + GEMM (runs concurrently with CSR build)
    kzW<<<128, 256>>>(W);
    f1<<<K1_TILES, 256>>>(x, attn_l, attn_r);

    cudaStreamWaitEvent(0, evJoin, 0);                 // join before gather
    k6_gather<<<(NN + 7) / 8, 256>>>(out);

    cudaEventDestroy(evFork);
    cudaEventDestroy(evJoin);
    cudaStreamDestroy(s2);
}